// round 5
// baseline (speedup 1.0000x reference)
#include <cuda_runtime.h>
#include <cuda_bf16.h>
#include <cstdint>

// Problem constants
#define T_SEQ 65536
#define F_IN  512
#define H_DIM 64
#define G_DIM 256    // 4*H
#define NT2   (T_SEQ / 2)

typedef unsigned long long ull;

// Scratch (allocation-free rule: __device__ globals)
// g_xg2[tb*256 + p] = {pre(2tb), pre(2tb+1)} for recurrence thread p.
__device__ __align__(16) float2 g_xg2[(size_t)NT2 * G_DIM];
__device__ float g_hfin[H_DIM];

// ---------------- packed f32x2 helpers ----------------
static __device__ __forceinline__ ull fma2(ull a, ull b, ull c) {
    ull d;
    asm("fma.rn.f32x2 %0, %1, %2, %3;" : "=l"(d) : "l"(a), "l"(b), "l"(c));
    return d;
}
static __device__ __forceinline__ ull add2(ull a, ull b) {
    ull d;
    asm("add.rn.f32x2 %0, %1, %2;" : "=l"(d) : "l"(a), "l"(b));
    return d;
}
static __device__ __forceinline__ float2 upk(ull a) {
    float2 r;
    asm("mov.b64 {%0, %1}, %2;" : "=f"(r.x), "=f"(r.y) : "l"(a));
    return r;
}

// ---------------- single-instruction MUFU.TANH ----------------
static __device__ __forceinline__ float tanhap(float x) {
    float r;
    asm("tanh.approx.f32 %0, %1;" : "=f"(r) : "f"(x));
    return r;
}

// Recurrence thread for gate g of unit u:
// warp w = u>>3 owns units [8w, 8w+8); lanes 4*(u&7)+g hold gates i,f,g,o.
static __device__ __forceinline__ int map_tid(int g, int u) {
    return ((u >> 3) << 5) + ((u & 7) << 2) + g;
}

// =====================================================================
// Kernel 1: xg = x @ W_ih.T + (b_ih + b_hh), permuted into g_xg2.
// =====================================================================
__global__ void gemm_xg(const float* __restrict__ x,
                        const float* __restrict__ Wih,
                        const float* __restrict__ bih,
                        const float* __restrict__ bhh) {
    __shared__ float xs[64][17];
    __shared__ float ws[64][17];
    const int tid = threadIdx.x;           // 0..255
    const int tx = tid & 15, ty = tid >> 4;
    const int row0 = blockIdx.x * 64;      // t-tile base
    const int col0 = blockIdx.y * 64;      // gate-row tile base

    float acc[4][4];
#pragma unroll
    for (int i = 0; i < 4; i++)
#pragma unroll
        for (int j = 0; j < 4; j++) acc[i][j] = 0.0f;

    const int l = tid * 4;
    const int lr = l >> 4, lk = l & 15;

    for (int kb = 0; kb < F_IN; kb += 16) {
        float4 xv = *(const float4*)(x + (size_t)(row0 + lr) * F_IN + kb + lk);
        float4 wv = *(const float4*)(Wih + (size_t)(col0 + lr) * F_IN + kb + lk);
        xs[lr][lk] = xv.x; xs[lr][lk + 1] = xv.y; xs[lr][lk + 2] = xv.z; xs[lr][lk + 3] = xv.w;
        ws[lr][lk] = wv.x; ws[lr][lk + 1] = wv.y; ws[lr][lk + 2] = wv.z; ws[lr][lk + 3] = wv.w;
        __syncthreads();
#pragma unroll
        for (int kk = 0; kk < 16; kk++) {
            float a[4], b[4];
#pragma unroll
            for (int i = 0; i < 4; i++) a[i] = xs[ty * 4 + i][kk];
#pragma unroll
            for (int j = 0; j < 4; j++) b[j] = ws[tx * 4 + j][kk];
#pragma unroll
            for (int i = 0; i < 4; i++)
#pragma unroll
                for (int j = 0; j < 4; j++) acc[i][j] = fmaf(a[i], b[j], acc[i][j]);
        }
        __syncthreads();
    }

    const int t0 = row0 + ty * 4;
    const int tb0 = t0 >> 1;
#pragma unroll
    for (int j = 0; j < 4; j++) {
        const int col = col0 + tx * 4 + j;
        const float bj = bih[col] + bhh[col];
        const int gg = col >> 6;            // gate 0=i 1=f 2=g 3=o
        const int uu = col & 63;
        const int p = map_tid(gg, uu);
        g_xg2[(size_t)tb0 * G_DIM + p]       = make_float2(acc[0][j] + bj, acc[1][j] + bj);
        g_xg2[(size_t)(tb0 + 1) * G_DIM + p] = make_float2(acc[2][j] + bj, acc[3][j] + bj);
    }
}

// =====================================================================
// Kernel 2: persistent single-block LSTM recurrence, 256 threads
// (2 warps per SMSP so latency bubbles get cross-filled).
// Thread = one gate row (gate gg of unit u); exchange via 2 shfl.xor.
// One __syncthreads per step; double-buffered h in smem.
// =====================================================================
__global__ void __launch_bounds__(256, 1)
lstm_rec(const float* __restrict__ Whh,
         const float* __restrict__ h0,
         const float* __restrict__ c0) {
    __shared__ __align__(16) float h_sh[2][H_DIM];
    const int tid = threadIdx.x;          // 0..255
    const int w = tid >> 5, l = tid & 31;
    const int u = (w << 3) + (l >> 2);    // hidden unit
    const int gg = l & 3;                 // gate 0=i 1=f 2=g 3=o
    const int r = (gg << 6) | u;          // W_hh row
    const bool fl = (gg == 1);            // f-lane owns c and h

    // W_hh row -> 32 packed f32x2 registers
    ull wr_[32];
    {
        const ulonglong2* pr_ = (const ulonglong2*)(Whh + (size_t)r * H_DIM);
#pragma unroll
        for (int i = 0; i < 16; i++) {
            ulonglong2 v = pr_[i];
            wr_[2 * i] = v.x;
            wr_[2 * i + 1] = v.y;
        }
    }

    // activation: gate 2 (g) -> tanh ; others -> sigmoid = 0.5*tanh(0.5x)+0.5
    const float s0 = (gg == 2) ? 1.0f : 0.5f;   // pre-scale
    const float s1 = s0;                        // post-scale
    const float s2 = (gg == 2) ? 0.0f : 0.5f;   // offset

    float c = fl ? c0[u] : 0.0f;
    float h = 0.0f;
    if (tid < H_DIM) h_sh[0][tid] = h0[tid];

#define STEP(XV, RB, WB) do {                                                 \
        __syncthreads();                                                      \
        const ulonglong2* hp = (const ulonglong2*)h_sh[RB];                   \
        ull a0 = 0, a1 = 0, a2 = 0, a3 = 0;                                   \
        _Pragma("unroll")                                                     \
        for (int i = 0; i < 8; i++) {                                         \
            ulonglong2 hv = hp[2 * i], hw = hp[2 * i + 1];                    \
            a0 = fma2(hv.x, wr_[4 * i + 0], a0);                              \
            a1 = fma2(hv.y, wr_[4 * i + 1], a1);                              \
            a2 = fma2(hw.x, wr_[4 * i + 2], a2);                              \
            a3 = fma2(hw.y, wr_[4 * i + 3], a3);                              \
        }                                                                     \
        float2 s = upk(add2(add2(a0, a1), add2(a2, a3)));                     \
        float pre = (XV) + s.x + s.y;                                         \
        float v = fmaf(s1, tanhap(s0 * pre), s2);                             \
        /* xor2: i<->g, f<->o */                                              \
        float pv = __shfl_xor_sync(0xffffffffu, v, 2);                        \
        float pr = v * pv;                 /* lane i: i*g~ */                 \
        float prx = __shfl_xor_sync(0xffffffffu, pr, 1); /* f-lane gets it */ \
        if (fl) {                                                             \
            c = fmaf(v, c, prx);           /* c = f*c + i*g~ */               \
            h = pv * tanhap(c);            /* pv = o on the f-lane */         \
            h_sh[WB][u] = h;                                                  \
        }                                                                     \
    } while (0)

    // Streamed xg: one LDG.64 per 2 steps, prefetched 2 blocks ahead.
    float2 x0 = g_xg2[tid];
    float2 x1 = g_xg2[G_DIM + tid];
    for (int tb = 0; tb < NT2; tb++) {
        float2 x2 = x1;
        if (tb + 2 < NT2) x2 = g_xg2[(size_t)(tb + 2) * G_DIM + tid];
        STEP(x0.x, 0, 1);
        STEP(x0.y, 1, 0);
        x0 = x1; x1 = x2;
    }
#undef STEP

    if (fl) g_hfin[u] = h;
}

// =====================================================================
// Kernel 3: out[f] = sigmoid(h_last . W_fc[f] + b_fc[f]),  f < 512
// =====================================================================
__global__ void fc_out(const float* __restrict__ Wfc,
                       const float* __restrict__ bfc,
                       float* __restrict__ out) {
    __shared__ float hsm[H_DIM];
    const int tid = threadIdx.x;   // 0..511
    if (tid < H_DIM) hsm[tid] = g_hfin[tid];
    __syncthreads();
    float acc = bfc[tid];
    const float* wr = Wfc + (size_t)tid * H_DIM;
#pragma unroll
    for (int k = 0; k < H_DIM; k++) acc = fmaf(wr[k], hsm[k], acc);
    out[tid] = 1.0f / (1.0f + __expf(-acc));
}

extern "C" void kernel_launch(void* const* d_in, const int* in_sizes, int n_in,
                              void* d_out, int out_size) {
    const float* x   = (const float*)d_in[0];
    const float* h0  = (const float*)d_in[1];
    const float* c0  = (const float*)d_in[2];
    const float* Wih = (const float*)d_in[3];
    const float* Whh = (const float*)d_in[4];
    const float* bih = (const float*)d_in[5];
    const float* bhh = (const float*)d_in[6];
    const float* Wfc = (const float*)d_in[7];
    const float* bfc = (const float*)d_in[8];
    float* out = (float*)d_out;

    dim3 ggrid(T_SEQ / 64, G_DIM / 64);
    gemm_xg<<<ggrid, 256>>>(x, Wih, bih, bhh);
    lstm_rec<<<1, 256>>>(Whh, h0, c0);
    fc_out<<<1, 512>>>(Wfc, bfc, out);
}

// round 6
// speedup vs baseline: 1.6822x; 1.6822x over previous
#include <cuda_runtime.h>
#include <cuda_bf16.h>
#include <cstdint>

// Problem constants
#define T_SEQ 65536
#define F_IN  512
#define H_DIM 64
#define G_DIM 256    // 4*H
#define NT2   (T_SEQ / 2)

typedef unsigned long long ull;

// Scratch (allocation-free rule: __device__ globals)
// Slot streams, padded +2 blocks so the prefetch is unconditional.
__device__ __align__(16) float2 g_xgA[(size_t)(NT2 + 2) * 128];
__device__ __align__(16) float2 g_xgB[(size_t)(NT2 + 2) * 128];
__device__ float g_hfin[H_DIM];

// ---------------- packed f32x2 helpers ----------------
static __device__ __forceinline__ ull fma2(ull a, ull b, ull c) {
    ull d;
    asm("fma.rn.f32x2 %0, %1, %2, %3;" : "=l"(d) : "l"(a), "l"(b), "l"(c));
    return d;
}
static __device__ __forceinline__ ull add2(ull a, ull b) {
    ull d;
    asm("add.rn.f32x2 %0, %1, %2;" : "=l"(d) : "l"(a), "l"(b));
    return d;
}
static __device__ __forceinline__ float2 upk(ull a) {
    float2 r;
    asm("mov.b64 {%0, %1}, %2;" : "=f"(r.x), "=f"(r.y) : "l"(a));
    return r;
}
static __device__ __forceinline__ ull pk2(float x, float y) {
    ull r;
    asm("mov.b64 %0, {%1, %2};" : "=l"(r) : "f"(x), "f"(y));
    return r;
}

// ---------------- single-instruction MUFU.TANH ----------------
static __device__ __forceinline__ float tanhap(float x) {
    float r;
    asm("tanh.approx.f32 %0, %1;" : "=f"(r) : "f"(x));
    return r;
}

// Recurrence thread mapping for gate-row r (= g*64 + u):
// warp w = u>>4 owns units [16w,16w+16); even lane: gates (i,g); odd: (f,o)
static __device__ __forceinline__ int map_tid(int g, int u) {
    int odd = g & 1;                 // i,g -> even ; f,o -> odd
    return ((u >> 4) << 5) + ((u & 15) << 1) + odd;
}

// =====================================================================
// Kernel 1: xg = x @ W_ih.T + (b_ih + b_hh), permuted into slot streams.
// Sigmoid-gate entries (i, f, o) are pre-scaled by 0.5 (exact in fp32)
// so the recurrence activation needs no pre-multiply.
// =====================================================================
__global__ void gemm_xg(const float* __restrict__ x,
                        const float* __restrict__ Wih,
                        const float* __restrict__ bih,
                        const float* __restrict__ bhh) {
    __shared__ float xs[64][17];
    __shared__ float ws[64][17];
    const int tid = threadIdx.x;           // 0..255
    const int tx = tid & 15, ty = tid >> 4;
    const int row0 = blockIdx.x * 64;      // t-tile base
    const int col0 = blockIdx.y * 64;      // gate-row tile base

    float acc[4][4];
#pragma unroll
    for (int i = 0; i < 4; i++)
#pragma unroll
        for (int j = 0; j < 4; j++) acc[i][j] = 0.0f;

    const int l = tid * 4;
    const int lr = l >> 4, lk = l & 15;

    for (int kb = 0; kb < F_IN; kb += 16) {
        float4 xv = *(const float4*)(x + (size_t)(row0 + lr) * F_IN + kb + lk);
        float4 wv = *(const float4*)(Wih + (size_t)(col0 + lr) * F_IN + kb + lk);
        xs[lr][lk] = xv.x; xs[lr][lk + 1] = xv.y; xs[lr][lk + 2] = xv.z; xs[lr][lk + 3] = xv.w;
        ws[lr][lk] = wv.x; ws[lr][lk + 1] = wv.y; ws[lr][lk + 2] = wv.z; ws[lr][lk + 3] = wv.w;
        __syncthreads();
#pragma unroll
        for (int kk = 0; kk < 16; kk++) {
            float a[4], b[4];
#pragma unroll
            for (int i = 0; i < 4; i++) a[i] = xs[ty * 4 + i][kk];
#pragma unroll
            for (int j = 0; j < 4; j++) b[j] = ws[tx * 4 + j][kk];
#pragma unroll
            for (int i = 0; i < 4; i++)
#pragma unroll
                for (int j = 0; j < 4; j++) acc[i][j] = fmaf(a[i], b[j], acc[i][j]);
        }
        __syncthreads();
    }

    const int t0 = row0 + ty * 4;
    const int tb0 = t0 >> 1;
#pragma unroll
    for (int j = 0; j < 4; j++) {
        const int col = col0 + tx * 4 + j;
        const float bj = bih[col] + bhh[col];
        const int gg = col >> 6;            // gate 0=i 1=f 2=g 3=o
        const int uu = col & 63;
        const int p = map_tid(gg, uu);
        const float sc = (gg == 2) ? 1.0f : 0.5f;   // sigmoid pre-scale (exact)
        float2 lo = make_float2(sc * (acc[0][j] + bj), sc * (acc[1][j] + bj));
        float2 hi = make_float2(sc * (acc[2][j] + bj), sc * (acc[3][j] + bj));
        float2* buf = (gg >= 2) ? g_xgB : g_xgA;    // slot B = gates g,o
        buf[(size_t)tb0 * 128 + p] = lo;
        buf[(size_t)(tb0 + 1) * 128 + p] = hi;
    }
}

// =====================================================================
// Kernel 2: persistent single-block LSTM recurrence, 128 threads
// (4 warps, 1 per SMSP — R5 showed more warps regress the barrier).
// Even lane computes gates (i, g) of unit u, odd lane (f, o).
// One __syncthreads per step; gate product crosses via one shfl.
// Weights + xg pre-scaled by 0.5 for sigmoid gates; XV folded into
// the accumulator init -> shorter serial tail.
// =====================================================================
__global__ void __launch_bounds__(128, 1)
lstm_rec(const float* __restrict__ Whh,
         const float* __restrict__ h0,
         const float* __restrict__ c0) {
    __shared__ __align__(16) float h_sh[2][H_DIM];
    const int tid = threadIdx.x;          // 0..127
    const int w = tid >> 5, l = tid & 31;
    const int u = (w << 4) + (l >> 1);    // hidden unit
    const int odd = l & 1;
    const int rA = (odd ? 64 : 0) + u;    // i or f   (sigmoid: pre-scale 0.5)
    const int rB = (odd ? 192 : 128) + u; // g or o   (tanh: 1.0 / sigmoid: 0.5)
    const float scA = 0.5f;
    const float scB = odd ? 0.5f : 1.0f;

    // W_hh rows -> packed f32x2 registers, pre-scaled (x0.5 is exact)
    ull wA[32], wB[32];
    {
        const float2* pa = (const float2*)(Whh + (size_t)rA * H_DIM);
        const float2* pb = (const float2*)(Whh + (size_t)rB * H_DIM);
#pragma unroll
        for (int i = 0; i < 32; i++) {
            float2 va = pa[i], vb = pb[i];
            wA[i] = pk2(scA * va.x, scA * va.y);
            wB[i] = pk2(scB * vb.x, scB * vb.y);
        }
    }

    // post-scale/offset: vA = 0.5*tanh(preA)+0.5 (sigmoid);
    // vB: even = tanh(preB); odd = 0.5*tanh(preB)+0.5
    const float aB = odd ? 0.5f : 1.0f;
    const float oB = odd ? 0.5f : 0.0f;

    float c = odd ? c0[u] : 0.0f;
    float h = 0.0f;
    if (tid < H_DIM) h_sh[0][tid] = h0[tid];

#define STEP(XA, XB, RB, WB) do {                                             \
        __syncthreads();                                                      \
        const ulonglong2* hp = (const ulonglong2*)h_sh[RB];                   \
        ull a0 = (ull)__float_as_uint(XA);  /* {XA, 0} */                     \
        ull b0 = (ull)__float_as_uint(XB);  /* {XB, 0} */                     \
        ull a1 = 0, a2 = 0, a3 = 0;                                           \
        ull b1 = 0, b2 = 0, b3 = 0;                                           \
        _Pragma("unroll")                                                     \
        for (int i = 0; i < 8; i++) {                                         \
            ulonglong2 hv = hp[2 * i], hw = hp[2 * i + 1];                    \
            a0 = fma2(hv.x, wA[4 * i + 0], a0);                               \
            b0 = fma2(hv.x, wB[4 * i + 0], b0);                               \
            a1 = fma2(hv.y, wA[4 * i + 1], a1);                               \
            b1 = fma2(hv.y, wB[4 * i + 1], b1);                               \
            a2 = fma2(hw.x, wA[4 * i + 2], a2);                               \
            b2 = fma2(hw.x, wB[4 * i + 2], b2);                               \
            a3 = fma2(hw.y, wA[4 * i + 3], a3);                               \
            b3 = fma2(hw.y, wB[4 * i + 3], b3);                               \
        }                                                                     \
        float2 sA = upk(add2(add2(a0, a1), add2(a2, a3)));                    \
        float2 sB = upk(add2(add2(b0, b1), add2(b2, b3)));                    \
        float vA = fmaf(0.5f, tanhap(sA.x + sA.y), 0.5f);   /* sigmoid */     \
        float vB = fmaf(aB, tanhap(sB.x + sB.y), oB);       /* tanh / sig */  \
        float pr = __shfl_sync(0xffffffffu, vA * vB, l & 30);  /* i*g~ */     \
        if (odd) {                                                            \
            c = fmaf(vA, c, pr);            /* c = f*c + i*g~ */              \
            h = vB * tanhap(c);             /* h = o*tanh(c) */               \
            h_sh[WB][u] = h;                                                  \
        }                                                                     \
    } while (0)

    // Streamed xg: one LDG.64 pair per 2 steps, prefetched 2 blocks ahead
    // (arrays padded, so no bounds predicate).
    float2 xA0 = g_xgA[tid],       xB0 = g_xgB[tid];
    float2 xA1 = g_xgA[128 + tid], xB1 = g_xgB[128 + tid];
    for (int tb = 0; tb < NT2; tb++) {
        float2 xA2 = g_xgA[(size_t)(tb + 2) * 128 + tid];
        float2 xB2 = g_xgB[(size_t)(tb + 2) * 128 + tid];
        STEP(xA0.x, xB0.x, 0, 1);
        STEP(xA0.y, xB0.y, 1, 0);
        xA0 = xA1; xA1 = xA2;
        xB0 = xB1; xB1 = xB2;
    }
#undef STEP

    if (odd) g_hfin[u] = h;
}

// =====================================================================
// Kernel 3: out[f] = sigmoid(h_last . W_fc[f] + b_fc[f]),  f < 512
// =====================================================================
__global__ void fc_out(const float* __restrict__ Wfc,
                       const float* __restrict__ bfc,
                       float* __restrict__ out) {
    __shared__ float hsm[H_DIM];
    const int tid = threadIdx.x;   // 0..511
    if (tid < H_DIM) hsm[tid] = g_hfin[tid];
    __syncthreads();
    float acc = bfc[tid];
    const float* wr = Wfc + (size_t)tid * H_DIM;
#pragma unroll
    for (int k = 0; k < H_DIM; k++) acc = fmaf(wr[k], hsm[k], acc);
    out[tid] = 1.0f / (1.0f + __expf(-acc));
}

extern "C" void kernel_launch(void* const* d_in, const int* in_sizes, int n_in,
                              void* d_out, int out_size) {
    const float* x   = (const float*)d_in[0];
    const float* h0  = (const float*)d_in[1];
    const float* c0  = (const float*)d_in[2];
    const float* Wih = (const float*)d_in[3];
    const float* Whh = (const float*)d_in[4];
    const float* bih = (const float*)d_in[5];
    const float* bhh = (const float*)d_in[6];
    const float* Wfc = (const float*)d_in[7];
    const float* bfc = (const float*)d_in[8];
    float* out = (float*)d_out;

    dim3 ggrid(T_SEQ / 64, G_DIM / 64);
    gemm_xg<<<ggrid, 256>>>(x, Wih, bih, bhh);
    lstm_rec<<<1, 128>>>(Whh, h0, c0);
    fc_out<<<1, 512>>>(Wfc, bfc, out);
}

// round 7
// speedup vs baseline: 2.2534x; 1.3396x over previous
#include <cuda_runtime.h>
#include <cuda_bf16.h>
#include <cstdint>

// Problem constants
#define T_SEQ 65536
#define F_IN  512
#define H_DIM 64
#define G_DIM 256    // 4*H
#define NT4   (T_SEQ / 4)

typedef unsigned long long ull;

// Scratch (allocation-free rule: __device__ globals)
// Slot streams as float4 (4 timesteps per load), padded +2 blocks so the
// prefetch needs no bounds predicate.
__device__ __align__(16) float4 g_xgA[(size_t)(NT4 + 2) * 128];
__device__ __align__(16) float4 g_xgB[(size_t)(NT4 + 2) * 128];
__device__ float g_hfin[H_DIM];

// ---------------- packed f32x2 helpers ----------------
static __device__ __forceinline__ ull fma2(ull a, ull b, ull c) {
    ull d;
    asm("fma.rn.f32x2 %0, %1, %2, %3;" : "=l"(d) : "l"(a), "l"(b), "l"(c));
    return d;
}
static __device__ __forceinline__ ull add2(ull a, ull b) {
    ull d;
    asm("add.rn.f32x2 %0, %1, %2;" : "=l"(d) : "l"(a), "l"(b));
    return d;
}
static __device__ __forceinline__ float2 upk(ull a) {
    float2 r;
    asm("mov.b64 {%0, %1}, %2;" : "=f"(r.x), "=f"(r.y) : "l"(a));
    return r;
}
static __device__ __forceinline__ ull pk2(float x, float y) {
    ull r;
    asm("mov.b64 %0, {%1, %2};" : "=l"(r) : "f"(x), "f"(y));
    return r;
}

// ---------------- single-instruction MUFU.TANH ----------------
static __device__ __forceinline__ float tanhap(float x) {
    float r;
    asm("tanh.approx.f32 %0, %1;" : "=f"(r) : "f"(x));
    return r;
}

// Recurrence thread mapping for gate-row r (= g*64 + u):
// warp w = u>>4 owns units [16w,16w+16); even lane: gates (i,g); odd: (f,o)
static __device__ __forceinline__ int map_tid(int g, int u) {
    int odd = g & 1;                 // i,g -> even ; f,o -> odd
    return ((u >> 4) << 5) + ((u & 15) << 1) + odd;
}

// =====================================================================
// Kernel 1: xg = x @ W_ih.T + (b_ih + b_hh), permuted into slot streams.
// Sigmoid-gate entries (i, f, o) pre-scaled by 0.5 (exact in fp32).
// Stream layout: g_xgA[tb4*128 + p] = {pre(4tb4+0..3)} (slot A), same for B.
// =====================================================================
__global__ void gemm_xg(const float* __restrict__ x,
                        const float* __restrict__ Wih,
                        const float* __restrict__ bih,
                        const float* __restrict__ bhh) {
    __shared__ float xs[64][17];
    __shared__ float ws[64][17];
    const int tid = threadIdx.x;           // 0..255
    const int tx = tid & 15, ty = tid >> 4;
    const int row0 = blockIdx.x * 64;      // t-tile base
    const int col0 = blockIdx.y * 64;      // gate-row tile base

    float acc[4][4];
#pragma unroll
    for (int i = 0; i < 4; i++)
#pragma unroll
        for (int j = 0; j < 4; j++) acc[i][j] = 0.0f;

    const int l = tid * 4;
    const int lr = l >> 4, lk = l & 15;

    for (int kb = 0; kb < F_IN; kb += 16) {
        float4 xv = *(const float4*)(x + (size_t)(row0 + lr) * F_IN + kb + lk);
        float4 wv = *(const float4*)(Wih + (size_t)(col0 + lr) * F_IN + kb + lk);
        xs[lr][lk] = xv.x; xs[lr][lk + 1] = xv.y; xs[lr][lk + 2] = xv.z; xs[lr][lk + 3] = xv.w;
        ws[lr][lk] = wv.x; ws[lr][lk + 1] = wv.y; ws[lr][lk + 2] = wv.z; ws[lr][lk + 3] = wv.w;
        __syncthreads();
#pragma unroll
        for (int kk = 0; kk < 16; kk++) {
            float a[4], b[4];
#pragma unroll
            for (int i = 0; i < 4; i++) a[i] = xs[ty * 4 + i][kk];
#pragma unroll
            for (int j = 0; j < 4; j++) b[j] = ws[tx * 4 + j][kk];
#pragma unroll
            for (int i = 0; i < 4; i++)
#pragma unroll
                for (int j = 0; j < 4; j++) acc[i][j] = fmaf(a[i], b[j], acc[i][j]);
        }
        __syncthreads();
    }

    // Thread's 4 t-rows (t0 multiple of 4) form exactly one float4 block.
    const int tb4 = (row0 + ty * 4) >> 2;
#pragma unroll
    for (int j = 0; j < 4; j++) {
        const int col = col0 + tx * 4 + j;
        const float bj = bih[col] + bhh[col];
        const int gg = col >> 6;            // gate 0=i 1=f 2=g 3=o
        const int uu = col & 63;
        const int p = map_tid(gg, uu);
        const float sc = (gg == 2) ? 1.0f : 0.5f;   // sigmoid pre-scale (exact)
        float4 o;
        o.x = sc * (acc[0][j] + bj);
        o.y = sc * (acc[1][j] + bj);
        o.z = sc * (acc[2][j] + bj);
        o.w = sc * (acc[3][j] + bj);
        float4* buf = (gg >= 2) ? g_xgB : g_xgA;    // slot B = gates g,o
        buf[(size_t)tb4 * 128 + p] = o;
    }
}

// =====================================================================
// Kernel 2: persistent single-block LSTM recurrence, 128 threads
// (4 warps, 1 per SMSP). Even lane: gates (i, g) of unit u; odd: (f, o).
// One __syncthreads per step; gate product crosses via one shfl.
// R4 dataflow (acc init 0, XV added post-reduce) + pre-scaled weights.
// =====================================================================
__global__ void __launch_bounds__(128, 1)
lstm_rec(const float* __restrict__ Whh,
         const float* __restrict__ h0,
         const float* __restrict__ c0) {
    __shared__ __align__(16) float h_sh[2][H_DIM];
    const int tid = threadIdx.x;          // 0..127
    const int w = tid >> 5, l = tid & 31;
    const int u = (w << 4) + (l >> 1);    // hidden unit
    const int odd = l & 1;
    const int rA = (odd ? 64 : 0) + u;    // i or f   (sigmoid: pre-scale 0.5)
    const int rB = (odd ? 192 : 128) + u; // g or o   (tanh: 1.0 / sigmoid: 0.5)
    const float scA = 0.5f;
    const float scB = odd ? 0.5f : 1.0f;

    // W_hh rows -> packed f32x2 registers, pre-scaled (x0.5 exact)
    ull wA[32], wB[32];
    {
        const float2* pa = (const float2*)(Whh + (size_t)rA * H_DIM);
        const float2* pb = (const float2*)(Whh + (size_t)rB * H_DIM);
#pragma unroll
        for (int i = 0; i < 32; i++) {
            float2 va = pa[i], vb = pb[i];
            wA[i] = pk2(scA * va.x, scA * va.y);
            wB[i] = pk2(scB * vb.x, scB * vb.y);
        }
    }

    // post-scale/offset: vA = 0.5*tanh(preA)+0.5 (sigmoid);
    // vB: even = tanh(preB); odd = 0.5*tanh(preB)+0.5
    const float aB = odd ? 0.5f : 1.0f;
    const float oB = odd ? 0.5f : 0.0f;

    float c = odd ? c0[u] : 0.0f;
    float h = 0.0f;
    if (tid < H_DIM) h_sh[0][tid] = h0[tid];

#define STEP(XA, XB, RB, WB) do {                                             \
        __syncthreads();                                                      \
        const ulonglong2* hp = (const ulonglong2*)h_sh[RB];                   \
        ull a0 = 0, a1 = 0, a2 = 0, a3 = 0;                                   \
        ull b0 = 0, b1 = 0, b2 = 0, b3 = 0;                                   \
        _Pragma("unroll")                                                     \
        for (int i = 0; i < 8; i++) {                                         \
            ulonglong2 hv = hp[2 * i], hw = hp[2 * i + 1];                    \
            a0 = fma2(hv.x, wA[4 * i + 0], a0);                               \
            b0 = fma2(hv.x, wB[4 * i + 0], b0);                               \
            a1 = fma2(hv.y, wA[4 * i + 1], a1);                               \
            b1 = fma2(hv.y, wB[4 * i + 1], b1);                               \
            a2 = fma2(hw.x, wA[4 * i + 2], a2);                               \
            b2 = fma2(hw.x, wB[4 * i + 2], b2);                               \
            a3 = fma2(hw.y, wA[4 * i + 3], a3);                               \
            b3 = fma2(hw.y, wB[4 * i + 3], b3);                               \
        }                                                                     \
        float2 sA = upk(add2(add2(a0, a1), add2(a2, a3)));                    \
        float2 sB = upk(add2(add2(b0, b1), add2(b2, b3)));                    \
        float preA = (XA) + sA.x + sA.y;                                      \
        float preB = (XB) + sB.x + sB.y;                                      \
        float vA = fmaf(0.5f, tanhap(preA), 0.5f);   /* sigmoid (pre-scaled)*/\
        float vB = fmaf(aB, tanhap(preB), oB);       /* tanh / sigmoid */     \
        float pr = __shfl_sync(0xffffffffu, vA * vB, l & 30);  /* i*g~ */     \
        if (odd) {                                                            \
            c = fmaf(vA, c, pr);            /* c = f*c + i*g~ */              \
            h = vB * tanhap(c);             /* h = o*tanh(c) */               \
            h_sh[WB][u] = h;                                                  \
        }                                                                     \
    } while (0)

    // Streamed xg: one LDG.128 pair per 4 steps, prefetched 2 blocks ahead
    // (padded arrays -> no bounds predicate; unrolled ring -> pure renaming).
    float4 xA0 = g_xgA[tid],       xB0 = g_xgB[tid];
    float4 xA1 = g_xgA[128 + tid], xB1 = g_xgB[128 + tid];
    for (int tb = 0; tb < NT4; tb++) {
        float4 xA2 = g_xgA[(size_t)(tb + 2) * 128 + tid];
        float4 xB2 = g_xgB[(size_t)(tb + 2) * 128 + tid];
        STEP(xA0.x, xB0.x, 0, 1);
        STEP(xA0.y, xB0.y, 1, 0);
        STEP(xA0.z, xB0.z, 0, 1);
        STEP(xA0.w, xB0.w, 1, 0);
        xA0 = xA1; xA1 = xA2;
        xB0 = xB1; xB1 = xB2;
    }
#undef STEP

    if (odd) g_hfin[u] = h;
}

// =====================================================================
// Kernel 3: out[f] = sigmoid(h_last . W_fc[f] + b_fc[f]),  f < 512
// =====================================================================
__global__ void fc_out(const float* __restrict__ Wfc,
                       const float* __restrict__ bfc,
                       float* __restrict__ out) {
    __shared__ float hsm[H_DIM];
    const int tid = threadIdx.x;   // 0..511
    if (tid < H_DIM) hsm[tid] = g_hfin[tid];
    __syncthreads();
    float acc = bfc[tid];
    const float* wr = Wfc + (size_t)tid * H_DIM;
#pragma unroll
    for (int k = 0; k < H_DIM; k++) acc = fmaf(wr[k], hsm[k], acc);
    out[tid] = 1.0f / (1.0f + __expf(-acc));
}

extern "C" void kernel_launch(void* const* d_in, const int* in_sizes, int n_in,
                              void* d_out, int out_size) {
    const float* x   = (const float*)d_in[0];
    const float* h0  = (const float*)d_in[1];
    const float* c0  = (const float*)d_in[2];
    const float* Wih = (const float*)d_in[3];
    const float* Whh = (const float*)d_in[4];
    const float* bih = (const float*)d_in[5];
    const float* bhh = (const float*)d_in[6];
    const float* Wfc = (const float*)d_in[7];
    const float* bfc = (const float*)d_in[8];
    float* out = (float*)d_out;

    dim3 ggrid(T_SEQ / 64, G_DIM / 64);
    gemm_xg<<<ggrid, 256>>>(x, Wih, bih, bhh);
    lstm_rec<<<1, 128>>>(Whh, h0, c0);
    fc_out<<<1, 512>>>(Wfc, bfc, out);
}